// round 7
// baseline (speedup 1.0000x reference)
#include <cuda_runtime.h>

// ---------------------------------------------------------------------------
// Problem constants
// ---------------------------------------------------------------------------
constexpr int Bn  = 8;
constexpr int CH  = 128;
constexpr int H   = 80;
constexpr int W   = 80;
constexpr int HW  = H * W;
constexpr int MID = 16;
constexpr int KD  = CH * 9;          // 1152
constexpr float EPS = 1e-5f;

// ---------------------------------------------------------------------------
// Scratch
// ---------------------------------------------------------------------------
__device__ float g_h[Bn * CH * HW];
__device__ float g_off[Bn * 27 * HW];
__device__ float g_vals[(size_t)Bn * CH * 9 * HW];   // [b][c*9+k][y][x]
__device__ float g_iral[Bn * CH * HW];
__device__ float g_g1[Bn * MID * HW];
__device__ float g_gate[Bn * HW];
__device__ float g_fin[Bn * 2 * CH * HW];            // fused conv input concat
// duplicated (w,w) weights, bank-permuted for conflict-free packed LDS
__device__ float2 g_w0d[2 * CH * 9 * CH];            // 2304 x 128
__device__ float2 g_wfd[2 * CH * 9 * CH];            // 2304 x 128
__device__ float2 g_wdd[KD * CH];                    // 1152 x 128
__device__ float2 g_w2d[KD * 32];                    // 1152 x 32 (27 padded)

#define DEV __device__ __forceinline__
typedef unsigned long long ull;
typedef unsigned int u32;

DEV float sigm_(float x) { return 1.0f / (1.0f + __expf(-x)); }
DEV float silu_(float x) { return x * sigm_(x); }

DEV void ffma2(ull& d, ull a, ull b) {
    asm("fma.rn.f32x2 %0, %1, %2, %0;" : "+l"(d) : "l"(a), "l"(b));
}
DEV void unpack2(ull u, float& x, float& y) {
    asm("mov.b64 {%0, %1}, %2;" : "=f"(x), "=f"(y) : "l"(u));
}
DEV u32 smem_u32(const void* p) {
    u32 a; asm("{ .reg .u64 t; cvta.to.shared.u64 t, %1; cvt.u32.u64 %0, t; }" : "=r"(a) : "l"(p));
    return a;
}
DEV void cp4(u32 dst, const float* src) {
    asm volatile("cp.async.ca.shared.global [%0], [%1], 4;" :: "r"(dst), "l"(src) : "memory");
}
DEV void cp8(u32 dst, const float2* src) {
    asm volatile("cp.async.ca.shared.global [%0], [%1], 8;" :: "r"(dst), "l"(src) : "memory");
}
DEV void cp4z(u32 dst, const float* src, bool ok) {
    int sz = ok ? 4 : 0;
    asm volatile("cp.async.ca.shared.global [%0], [%1], 4, %2;"
                 :: "r"(dst), "l"(src), "r"(sz) : "memory");
}
DEV void cp_commit() { asm volatile("cp.async.commit_group;" ::: "memory"); }
DEV void cp_wait1()  { asm volatile("cp.async.wait_group 1;" ::: "memory"); }
DEV void cp_wait0()  { asm volatile("cp.async.wait_group 0;" ::: "memory"); }

// ---------------------------------------------------------------------------
// Weight prep: duplicate to (w,w) float2 with bank permutation.
// For RCO=4 blocks of 64 couts: col = by*64 + q, q = 2t + 32*jh + jl
//   <-> co_local = 4t + 2*jh + jl  (thread t reads 2 conflict-free LDS.128)
// IDENT=1 (RCO=2): col == co (single LDS.128 per thread, identity map).
// src layout: [co][K] row-major (K = CIN*9 or KD).
// ---------------------------------------------------------------------------
template <int IDENT>
__global__ __launch_bounds__(256)
void prep_w_kernel(const float* __restrict__ src, float2* __restrict__ dst,
                   int K, int cols, int cout) {
    int idx = blockIdx.x * 256 + threadIdx.x;
    if (idx >= K * cols) return;
    int r = idx / cols, col = idx % cols;
    int co;
    if (IDENT) {
        co = col;
    } else {
        int by = col >> 6, q = col & 63;
        int jh = q >> 5, rr = q & 31, t = rr >> 1, jl = rr & 1;
        co = by * 64 + 4 * t + 2 * jh + jl;
    }
    float v = (co < cout) ? src[(size_t)co * K + r] : 0.0f;
    dst[idx] = make_float2(v, v);
}

// ---------------------------------------------------------------------------
// 3x3 tiled conv, cp.async double-buffered, pre-duplicated packed weights.
//   MODE 0: concat(rgb, ir)  Cin=256 -> g_h   (silu(v+b))
//   MODE 1: g_fin            Cin=256 -> out   (silu(bn)+res)
//   MODE 3: g_h              Cin=128 -> g_off (v+b)
// ---------------------------------------------------------------------------
template <int MODE>
__global__ __launch_bounds__(256)
void conv_kernel(const float* __restrict__ A, const float* __restrict__ Bp,
                 const float2* __restrict__ wf2,
                 const float* __restrict__ bias_or_bn,
                 const float* __restrict__ res_scale,
                 float* __restrict__ out_param) {
    constexpr int KS2  = 9;
    constexpr int CIN  = (MODE == 3) ? CH : 2 * CH;
    constexpr int COUT = (MODE == 3) ? 27 : CH;
    constexpr int RCO  = (MODE == 3) ? 2 : 4;
    constexpr int CO_TILE = 16 * RCO;
    constexpr int WCOLS = (MODE == 3) ? 32 : 128;   // f2 cols in prepped weights
    constexpr int CC   = 8;
    constexpr int S    = CC * KS2;                  // 72
    constexpr int XW   = W + 2;
    constexpr int SM_WF2 = S * CO_TILE;             // float2 per weight buffer
    constexpr int SM_IF  = CC * 3 * XW;             // float2 per input buffer
    constexpr int NCK  = CIN / CC;

    extern __shared__ char smc[];
    float2* sW = (float2*)smc;                         // [2][SM_WF2]
    float2* sI = (float2*)(smc + 2 * SM_WF2 * 8);      // [2][SM_IF]

    const int tid = threadIdx.x;
    const int tco = tid & 15;
    const int tpx = tid >> 4;
    const int x0  = tpx * 5;
    const int b   = blockIdx.x / (H / 2);
    const int y0  = (blockIdx.x % (H / 2)) * 2;
    const int co_base = blockIdx.y * CO_TILE;

    const u32 swb = smem_u32(sW);
    const u32 sib = smem_u32(sI);

    ull acc[RCO][5];
#pragma unroll
    for (int r = 0; r < RCO; r++)
#pragma unroll
        for (int p = 0; p < 5; p++) acc[r][p] = 0ull;

    auto chan_ptr = [&](int ci) -> const float* {
        if (MODE == 0) return (ci < CH) ? A + (size_t)(b * CH + ci) * HW
                                        : Bp + (size_t)(b * CH + (ci - CH)) * HW;
        else if (MODE == 1) return g_fin + (size_t)(b * 2 * CH + ci) * HW;
        else return g_h + (size_t)(b * CH + ci) * HW;
    };

    auto stage = [&](int ck, int buf) {
        const int ci0 = ck * CC;
        // weights: contiguous duplicated f2 copy
        const float2* wsrc = wf2 + (size_t)(ci0 * 9) * WCOLS + co_base;
#pragma unroll
        for (int i = 0; i < (S * CO_TILE) / 256; i++) {
            int idx = i * 256 + tid;
            int s = idx / CO_TILE, q = idx % CO_TILE;
            cp8(swb + (u32)(buf * SM_WF2 + idx) * 8u, wsrc + (size_t)s * WCOLS + q);
        }
        // inputs (row-pair interleaved float2), zfill halo
        for (int idx = tid; idx < CC * 3 * XW; idx += 256) {
            int ci  = idx / (3 * XW);
            int rem = idx % (3 * XW);
            int ry  = rem / XW;
            int xx  = rem % XW;
            int gx  = xx - 1;
            int gy0 = y0 - 1 + ry;
            int gy1 = gy0 + 1;
            bool okx = (gx >= 0) && (gx < W);
            const float* src = chan_ptr(ci0 + ci) + gy0 * W + gx;
            u32 dst = sib + (u32)(buf * SM_IF + (ci * 3 + ry) * XW + xx) * 8u;
            cp4z(dst,     src,     okx && (gy0 >= 0) && (gy0 < H));
            cp4z(dst + 4, src + W, okx && (gy1 < H));
        }
        cp_commit();
    };

    stage(0, 0);

    for (int ck = 0; ck < NCK; ck++) {
        const int buf = ck & 1;
        if (ck + 1 < NCK) { stage(ck + 1, buf ^ 1); cp_wait1(); }
        else              { cp_wait0(); }
        __syncthreads();

        const ulonglong2* wq = (const ulonglong2*)(sW + buf * SM_WF2);
        const float2* ibuf = sI + buf * SM_IF;
        for (int ci = 0; ci < CC; ++ci) {
#pragma unroll
            for (int ky = 0; ky < 3; ky++) {
                const ull* ip = reinterpret_cast<const ull*>(&ibuf[(ci * 3 + ky) * XW + x0]);
                ull vv[7];
#pragma unroll
                for (int j = 0; j < 7; j++) vv[j] = ip[j];
#pragma unroll
                for (int kx = 0; kx < 3; kx++) {
                    const int s = ci * KS2 + ky * 3 + kx;
                    ull w2[RCO];
                    if (RCO == 4) {
                        ulonglong2 wa = wq[s * 32 + tco];
                        ulonglong2 wb = wq[s * 32 + 16 + tco];
                        w2[0] = wa.x; w2[1] = wa.y; w2[2] = wb.x; w2[3] = wb.y;
                    } else {
                        ulonglong2 wa = wq[s * 16 + tco];
                        w2[0] = wa.x; w2[1] = wa.y;
                    }
#pragma unroll
                    for (int p = 0; p < 5; p++)
#pragma unroll
                        for (int r = 0; r < RCO; r++) ffma2(acc[r][p], w2[r], vv[kx + p]);
                }
            }
        }
        __syncthreads();
    }

    float* optr = (MODE == 0) ? g_h : (MODE == 3) ? g_off : out_param;
#pragma unroll
    for (int r = 0; r < RCO; r++) {
        int co = co_base + tco * RCO + r;
        if (co >= COUT) continue;
        float bnb, bns = 1.0f, rs = 0.0f;
        if (MODE == 1) {
            float gm = bias_or_bn[co];
            float bt = bias_or_bn[COUT + co];
            float mn = bias_or_bn[2 * COUT + co];
            float vr = bias_or_bn[3 * COUT + co];
            bns = gm * rsqrtf(vr + EPS);
            bnb = bt - mn * bns;
            rs  = *res_scale;
        } else {
            bnb = bias_or_bn[co];
        }
#pragma unroll
        for (int p = 0; p < 5; p++) {
            int x = x0 + p;
            int o0 = ((b * COUT + co) * H + y0) * W + x;
            int o1 = o0 + W;
            float a0, a1;
            unpack2(acc[r][p], a0, a1);
            if (MODE == 0) {
                optr[o0] = silu_(a0 + bnb);
                optr[o1] = silu_(a1 + bnb);
            } else if (MODE == 1) {
                optr[o0] = silu_(a0 * bns + bnb) + rs * g_iral[o0];
                optr[o1] = silu_(a1 * bns + bnb) + rs * g_iral[o1];
            } else {
                optr[o0] = a0 + bnb;
                optr[o1] = a1 + bnb;
            }
        }
    }
}

// ---------------------------------------------------------------------------
// DCN 1x1 conv (Cin=1152 -> 128), cp.async double-buffered, packed weights
// ---------------------------------------------------------------------------
constexpr int DCC   = 32;
constexpr int DCO_T = 64;
constexpr int DSM_W2 = DCC * DCO_T;           // float2 per weight buffer
constexpr int DSM_I  = DCC * W;               // float2 per input buffer
constexpr int DCN_SMEM = (2 * DSM_W2 + 2 * DSM_I) * 8;   // 73728 B

__global__ __launch_bounds__(256)
void dcn_conv_kernel(const float* __restrict__ bias) {
    extern __shared__ char dsmc[];
    float2* sW = (float2*)dsmc;                      // [2][DSM_W2]
    float2* sI = (float2*)(dsmc + 2 * DSM_W2 * 8);   // [2][DSM_I]

    const int tid = threadIdx.x;
    const int tco = tid & 15;
    const int tpx = tid >> 4;
    const int x0  = tpx * 5;
    const int b   = blockIdx.x / (H / 2);
    const int y0  = (blockIdx.x % (H / 2)) * 2;
    const int co_base = blockIdx.y * DCO_T;

    const u32 swb = smem_u32(sW);
    const u32 sib = smem_u32(sI);
    const float* vbase = g_vals + (size_t)b * KD * HW + (size_t)y0 * W;

    ull acc[4][5];
#pragma unroll
    for (int r = 0; r < 4; r++)
#pragma unroll
        for (int p = 0; p < 5; p++) acc[r][p] = 0ull;

    auto stage = [&](int ck, int buf) {
        const int ci0 = ck * DCC;
        const float2* wsrc = g_wdd + (size_t)ci0 * CH + co_base;
#pragma unroll
        for (int i = 0; i < (DCC * DCO_T) / 256; i++) {
            int idx = i * 256 + tid;
            int s = idx >> 6, q = idx & 63;
            cp8(swb + (u32)(buf * DSM_W2 + idx) * 8u, wsrc + (size_t)s * CH + q);
        }
#pragma unroll 2
        for (int i = 0; i < DSM_I / 256; i++) {
            int idx = i * 256 + tid;
            int ci = idx / W, xx = idx % W;
            const float* src = vbase + (size_t)(ci0 + ci) * HW + xx;
            u32 dst = sib + (u32)(buf * DSM_I + ci * W + xx) * 8u;
            cp4(dst, src);
            cp4(dst + 4, src + W);
        }
        cp_commit();
    };

    stage(0, 0);

    constexpr int NCK = KD / DCC;
    for (int ck = 0; ck < NCK; ck++) {
        const int buf = ck & 1;
        if (ck + 1 < NCK) { stage(ck + 1, buf ^ 1); cp_wait1(); }
        else              { cp_wait0(); }
        __syncthreads();

        const ulonglong2* wq = (const ulonglong2*)(sW + buf * DSM_W2);
        const float2* ibuf = sI + buf * DSM_I;
#pragma unroll 4
        for (int ci = 0; ci < DCC; ++ci) {
            const ull* ip = reinterpret_cast<const ull*>(&ibuf[ci * W + x0]);
            ull vv[5];
#pragma unroll
            for (int p = 0; p < 5; p++) vv[p] = ip[p];
            ulonglong2 wa = wq[ci * 32 + tco];
            ulonglong2 wb = wq[ci * 32 + 16 + tco];
            ull w2[4] = { wa.x, wa.y, wb.x, wb.y };
#pragma unroll
            for (int p = 0; p < 5; p++)
#pragma unroll
                for (int r = 0; r < 4; r++) ffma2(acc[r][p], w2[r], vv[p]);
        }
        __syncthreads();
    }

#pragma unroll
    for (int r = 0; r < 4; r++) {
        int co = co_base + tco * 4 + r;
        float bs = __ldg(&bias[co]);
#pragma unroll
        for (int p = 0; p < 5; p++) {
            int x = x0 + p;
            int o0 = ((b * CH + co) * H + y0) * W + x;
            float a0, a1;
            unpack2(acc[r][p], a0, a1);
            g_iral[o0]     = a0 + bs;
            g_iral[o0 + W] = a1 + bs;
        }
    }
}

// ---------------------------------------------------------------------------
// Deformable bilinear sampling -> g_vals[b][c*9+k][y][x]
// ---------------------------------------------------------------------------
__global__ __launch_bounds__(256)
void deform_kernel(const float* __restrict__ ir) {
    const int blk   = blockIdx.x;
    const int ytile = blk % 27;
    const int bk    = blk / 27;
    const int k     = bk % 9;
    const int b     = bk / 9;
    const int tid   = threadIdx.x;
    if (tid >= 240) return;
    const int y = ytile * 3 + tid / 80;
    const int x = tid % 80;
    if (y >= H) return;

    const float* obase = g_off + (b * 27) * HW + y * W + x;
    float oy = obase[(2 * k) * HW];
    float ox = obase[(2 * k + 1) * HW];
    float m  = sigm_(obase[(18 + k) * HW]);

    const int ky = k / 3 - 1;
    const int kx = k % 3 - 1;
    float ys = oy + (float)(ky + y);
    float xs = ox + (float)(kx + x);
    float fy = floorf(ys), fx = floorf(xs);
    float wy = ys - fy,    wx = xs - fx;
    int y0 = (int)fy, x0 = (int)fx;
    int y1 = y0 + 1,  x1 = x0 + 1;
    bool vy0 = (y0 >= 0) && (y0 < H);
    bool vy1 = (y1 >= 0) && (y1 < H);
    bool vx0 = (x0 >= 0) && (x0 < W);
    bool vx1 = (x1 >= 0) && (x1 < W);
    float w00 = (1.0f - wy) * (1.0f - wx) * m * ((vy0 && vx0) ? 1.0f : 0.0f);
    float w01 = (1.0f - wy) * wx          * m * ((vy0 && vx1) ? 1.0f : 0.0f);
    float w10 = wy          * (1.0f - wx) * m * ((vy1 && vx0) ? 1.0f : 0.0f);
    float w11 = wy          * wx          * m * ((vy1 && vx1) ? 1.0f : 0.0f);
    int cy0 = min(max(y0, 0), H - 1), cy1 = min(max(y1, 0), H - 1);
    int cx0 = min(max(x0, 0), W - 1), cx1 = min(max(x1, 0), W - 1);
    int i00 = cy0 * W + cx0, i01 = cy0 * W + cx1;
    int i10 = cy1 * W + cx0, i11 = cy1 * W + cx1;

    const float* ib = ir + b * CH * HW;
    float* vout = g_vals + ((size_t)b * CH * 9 + k) * HW + y * W + x;
#pragma unroll 4
    for (int c = 0; c < CH; c++) {
        const float* p = ib + c * HW;
        float v = w00 * __ldg(p + i00) + w01 * __ldg(p + i01)
                + w10 * __ldg(p + i10) + w11 * __ldg(p + i11);
        vout[(size_t)c * 9 * HW] = v;
    }
}

// ---------------------------------------------------------------------------
// Gate stage 1: 1x1 conv 256 -> 16 + BN + SiLU -> g_g1
// ---------------------------------------------------------------------------
__global__ __launch_bounds__(256)
void gate1_kernel(const float* __restrict__ rgb,
                  const float* __restrict__ wg1,
                  const float* __restrict__ bng1) {
    __shared__ float sg[2 * CH * MID];
    const int tid = threadIdx.x;
    for (int i = tid; i < 2 * CH * MID; i += 256) {
        int ci = i >> 4, o = i & 15;
        sg[i] = wg1[o * (2 * CH) + ci];
    }
    __syncthreads();
    const int idx = blockIdx.x * 256 + tid;
    if (idx >= Bn * HW) return;
    const int b = idx / HW, p = idx % HW;

    float acc[MID];
#pragma unroll
    for (int o = 0; o < MID; o++) acc[o] = 0.0f;

    const float* rp = rgb    + b * CH * HW + p;
    const float* ip = g_iral + b * CH * HW + p;
    for (int ci = 0; ci < CH; ci++) {
        float v = rp[ci * HW];
        const float* w = &sg[ci * MID];
#pragma unroll
        for (int o = 0; o < MID; o++) acc[o] += w[o] * v;
    }
    for (int ci = 0; ci < CH; ci++) {
        float v = ip[ci * HW];
        const float* w = &sg[(CH + ci) * MID];
#pragma unroll
        for (int o = 0; o < MID; o++) acc[o] += w[o] * v;
    }
#pragma unroll
    for (int o = 0; o < MID; o++) {
        float gm = bng1[o], bt = bng1[MID + o];
        float mn = bng1[2 * MID + o], vr = bng1[3 * MID + o];
        float sc = gm * rsqrtf(vr + EPS);
        g_g1[(b * MID + o) * HW + p] = silu_(acc[o] * sc + bt - mn * sc);
    }
}

// ---------------------------------------------------------------------------
// Gate stages 2+3, then materialize fused conv input g_fin
// ---------------------------------------------------------------------------
__global__ __launch_bounds__(256)
void gate23_kernel(const float* __restrict__ wg2,
                   const float* __restrict__ bng2,
                   const float* __restrict__ wg3,
                   const float* __restrict__ bg3,
                   const float* __restrict__ rgb) {
    const int idx = blockIdx.x * 256 + threadIdx.x;
    if (idx >= Bn * HW) return;
    const int b = idx / HW, p = idx % HW;
    const int y = p / W, x = p % W;

    float s3 = __ldg(bg3);
#pragma unroll
    for (int o = 0; o < MID; o++) {
        const float* gp = g_g1 + (b * MID + o) * HW;
        float s = 0.0f;
#pragma unroll
        for (int ky = 0; ky < 3; ky++) {
            int yy = y + ky - 1;
            if (yy < 0 || yy >= H) continue;
#pragma unroll
            for (int kx = 0; kx < 3; kx++) {
                int xx = x + kx - 1;
                if (xx < 0 || xx >= W) continue;
                s += gp[yy * W + xx] * __ldg(&wg2[o * 9 + ky * 3 + kx]);
            }
        }
        float gm = __ldg(&bng2[o]), bt = __ldg(&bng2[MID + o]);
        float mn = __ldg(&bng2[2 * MID + o]), vr = __ldg(&bng2[3 * MID + o]);
        float sc = gm * rsqrtf(vr + EPS);
        s3 += silu_(s * sc + bt - mn * sc) * __ldg(&wg3[o]);
    }
    float gv = sigm_(s3);
    g_gate[b * HW + p] = gv;

    const float* ip = g_iral + (size_t)b * CH * HW + p;
    const float* rp = rgb    + (size_t)b * CH * HW + p;
    float* f0 = g_fin + (size_t)b * 2 * CH * HW + p;
    float* f1 = f0 + (size_t)CH * HW;
    float om = 1.0f - gv;
#pragma unroll 4
    for (int c = 0; c < CH; c++) {
        f0[(size_t)c * HW] = gv * ip[(size_t)c * HW];
        f1[(size_t)c * HW] = om * rp[(size_t)c * HW];
    }
}

// ---------------------------------------------------------------------------
// Launcher
// ---------------------------------------------------------------------------
extern "C" void kernel_launch(void* const* d_in, const int* in_sizes, int n_in,
                              void* d_out, int out_size) {
    const float* rgb    = (const float*)d_in[0];
    const float* ir     = (const float*)d_in[1];
    const float* w_off1 = (const float*)d_in[2];
    const float* b_off1 = (const float*)d_in[3];
    const float* w_off2 = (const float*)d_in[4];
    const float* b_off2 = (const float*)d_in[5];
    const float* w_dcn  = (const float*)d_in[6];
    const float* b_dcn  = (const float*)d_in[7];
    const float* w_g1   = (const float*)d_in[8];
    const float* bn_g1  = (const float*)d_in[9];
    const float* w_g2   = (const float*)d_in[10];
    const float* bn_g2  = (const float*)d_in[11];
    const float* w_g3   = (const float*)d_in[12];
    const float* b_g3   = (const float*)d_in[13];
    const float* w_f    = (const float*)d_in[14];
    const float* bn_f   = (const float*)d_in[15];
    const float* rscale = (const float*)d_in[16];
    float* out = (float*)d_out;

    float2* w0d; cudaGetSymbolAddress((void**)&w0d, g_w0d);
    float2* wfd; cudaGetSymbolAddress((void**)&wfd, g_wfd);
    float2* w2d; cudaGetSymbolAddress((void**)&w2d, g_w2d);

    // double-buffered smem sizes (bytes)
    const int sm_big = 2 * (72 * 64 + 8 * 3 * 82) * 8;   // 105216 B (modes 0,1)
    const int sm_off = 2 * (72 * 32 + 8 * 3 * 82) * 8;   // 68352 B  (mode 3)

    cudaFuncSetAttribute(conv_kernel<0>, cudaFuncAttributeMaxDynamicSharedMemorySize, sm_big);
    cudaFuncSetAttribute(conv_kernel<1>, cudaFuncAttributeMaxDynamicSharedMemorySize, sm_big);
    cudaFuncSetAttribute(conv_kernel<3>, cudaFuncAttributeMaxDynamicSharedMemorySize, sm_off);
    cudaFuncSetAttribute(dcn_conv_kernel, cudaFuncAttributeMaxDynamicSharedMemorySize, DCN_SMEM);

    const int BX = Bn * (H / 2);   // 320 row-pair blocks

    // 0) weight prep (dup + permute)
    prep_w_kernel<0><<<(2304 * 128 + 255) / 256, 256>>>(w_off1, w0d, 2304, 128, 128);
    prep_w_kernel<0><<<(2304 * 128 + 255) / 256, 256>>>(w_f,    wfd, 2304, 128, 128);
    {
        float2* wdd; cudaGetSymbolAddress((void**)&wdd, g_wdd);
        prep_w_kernel<0><<<(1152 * 128 + 255) / 256, 256>>>(w_dcn, wdd, 1152, 128, 128);
    }
    prep_w_kernel<1><<<(1152 * 32 + 255) / 256, 256>>>(w_off2, w2d, 1152, 32, 27);

    // 1) h = silu(conv3x3(concat(rgb, ir)))
    conv_kernel<0><<<dim3(BX, 2), 256, sm_big>>>(rgb, ir, w0d, b_off1, nullptr, nullptr);
    // 2) offset/mask conv (27 ch)
    conv_kernel<3><<<dim3(BX, 1), 256, sm_off>>>(nullptr, nullptr, w2d, b_off2, nullptr, nullptr);
    // 3) deformable bilinear sampling * mask -> g_vals
    deform_kernel<<<Bn * 9 * 27, 256>>>(ir);
    // 4) ir_aligned = vals . w_dcn + b_dcn
    dcn_conv_kernel<<<dim3(BX, 2), 256, DCN_SMEM>>>(b_dcn);
    // 5) gate stage 1
    gate1_kernel<<<(Bn * HW + 255) / 256, 256>>>(rgb, w_g1, bn_g1);
    // 6) gate stages 2+3 + fused-input materialization
    gate23_kernel<<<(Bn * HW + 255) / 256, 256>>>(w_g2, bn_g2, w_g3, b_g3, rgb);
    // 7) fused conv + BN + SiLU + residual -> out
    conv_kernel<1><<<dim3(BX, 2), 256, sm_big>>>(nullptr, nullptr, wfd, bn_f, rscale, out);
}

// round 8
// speedup vs baseline: 1.1672x; 1.1672x over previous
#include <cuda_runtime.h>

// ---------------------------------------------------------------------------
// Problem constants
// ---------------------------------------------------------------------------
constexpr int Bn  = 8;
constexpr int CH  = 128;
constexpr int H   = 80;
constexpr int W   = 80;
constexpr int HW  = H * W;
constexpr int MID = 16;
constexpr int KD  = CH * 9;          // 1152
constexpr float EPS = 1e-5f;

// ---------------------------------------------------------------------------
// Scratch
// ---------------------------------------------------------------------------
__device__ float g_h[Bn * CH * HW];
__device__ float g_off[Bn * 27 * HW];
__device__ float g_vals[(size_t)Bn * CH * 9 * HW];   // [b][c*9+k][y][x]
__device__ float g_iral[Bn * CH * HW];
__device__ float g_g1[Bn * MID * HW];
__device__ float g_gate[Bn * HW];
__device__ float g_fin[Bn * 2 * CH * HW];            // fused conv input concat
// transposed weights [k][co] (row-major, contiguous in co) for cp16 staging
__device__ float g_w0t[2 * CH * 9 * CH];             // 2304 x 128
__device__ float g_wft[2 * CH * 9 * CH];             // 2304 x 128
__device__ float g_wdt[KD * CH];                     // 1152 x 128
__device__ float g_w2t[KD * 32];                     // 1152 x 32 (27 zero-padded)

#define DEV __device__ __forceinline__
typedef unsigned long long ull;
typedef unsigned int u32;

DEV float sigm_(float x) { return 1.0f / (1.0f + __expf(-x)); }
DEV float silu_(float x) { return x * sigm_(x); }

DEV void ffma2(ull& d, ull a, ull b) {
    asm("fma.rn.f32x2 %0, %1, %2, %0;" : "+l"(d) : "l"(a), "l"(b));
}
DEV ull dup2(float w) { ull u; asm("mov.b64 %0, {%1, %1};" : "=l"(u) : "f"(w)); return u; }
DEV void unpack2(ull u, float& x, float& y) {
    asm("mov.b64 {%0, %1}, %2;" : "=f"(x), "=f"(y) : "l"(u));
}
DEV u32 smem_u32(const void* p) {
    u32 a; asm("{ .reg .u64 t; cvta.to.shared.u64 t, %1; cvt.u32.u64 %0, t; }" : "=r"(a) : "l"(p));
    return a;
}
DEV void cp4(u32 dst, const float* src) {
    asm volatile("cp.async.ca.shared.global [%0], [%1], 4;" :: "r"(dst), "l"(src) : "memory");
}
DEV void cp16(u32 dst, const float* src) {
    asm volatile("cp.async.cg.shared.global [%0], [%1], 16;" :: "r"(dst), "l"(src) : "memory");
}
DEV void cp4z(u32 dst, const float* src, bool ok) {
    int sz = ok ? 4 : 0;
    asm volatile("cp.async.ca.shared.global [%0], [%1], 4, %2;"
                 :: "r"(dst), "l"(src), "r"(sz) : "memory");
}
DEV void cp_commit() { asm volatile("cp.async.commit_group;" ::: "memory"); }
DEV void cp_wait1()  { asm volatile("cp.async.wait_group 1;" ::: "memory"); }
DEV void cp_wait0()  { asm volatile("cp.async.wait_group 0;" ::: "memory"); }

// ---------------------------------------------------------------------------
// Weight transpose prep: src [co][K] -> dst [K][cols] (cols >= cout, padded 0)
// ---------------------------------------------------------------------------
__global__ __launch_bounds__(256)
void prep_w_kernel(const float* __restrict__ src, float* __restrict__ dst,
                   int K, int cols, int cout) {
    int idx = blockIdx.x * 256 + threadIdx.x;
    if (idx >= K * cols) return;
    int r = idx / cols, co = idx % cols;
    dst[idx] = (co < cout) ? src[(size_t)co * K + r] : 0.0f;
}

// ---------------------------------------------------------------------------
// 3x3 tiled conv, cp.async double-buffered, transposed-weight cp16 staging.
//   MODE 0: concat(rgb, ir)  Cin=256 -> g_h   (silu(v+b))
//   MODE 1: g_fin            Cin=256 -> out   (silu(bn)+res)
//   MODE 3: g_h              Cin=128 -> g_off (v+b)
// Block: 256 thr = 16 co-groups x 16 px-groups (5 px), 2 output rows.
// ---------------------------------------------------------------------------
template <int MODE>
__global__ __launch_bounds__(256)
void conv_kernel(const float* __restrict__ A, const float* __restrict__ Bp,
                 const float* __restrict__ wT,
                 const float* __restrict__ bias_or_bn,
                 const float* __restrict__ res_scale,
                 float* __restrict__ out_param) {
    constexpr int KS2  = 9;
    constexpr int CIN  = (MODE == 3) ? CH : 2 * CH;
    constexpr int COUT = (MODE == 3) ? 27 : CH;
    constexpr int RCO  = (MODE == 3) ? 2 : 4;
    constexpr int CO_TILE = 16 * RCO;
    constexpr int CO_PAD  = CO_TILE + 4;
    constexpr int WCOLS = (MODE == 3) ? 32 : 128;   // cols in transposed weights
    constexpr int CC   = 8;
    constexpr int S    = CC * KS2;                  // 72
    constexpr int XW   = W + 2;
    constexpr int SM_WF = S * CO_PAD;               // floats per weight buffer
    constexpr int SM_IF = CC * 3 * XW;              // float2 per input buffer
    constexpr int NCK  = CIN / CC;
    constexpr int NW16 = S * (CO_TILE / 4);         // cp16 ops per weight stage

    extern __shared__ float sm[];
    float*  sW = sm;                               // [2][SM_WF]
    float2* sI = (float2*)(sm + 2 * SM_WF);        // [2][SM_IF]

    const int tid = threadIdx.x;
    const int tco = tid & 15;
    const int tpx = tid >> 4;
    const int x0  = tpx * 5;
    const int b   = blockIdx.x / (H / 2);
    const int y0  = (blockIdx.x % (H / 2)) * 2;
    const int co_base = blockIdx.y * CO_TILE;

    const u32 swb = smem_u32(sW);
    const u32 sib = smem_u32(sI);

    ull acc[RCO][5];
#pragma unroll
    for (int r = 0; r < RCO; r++)
#pragma unroll
        for (int p = 0; p < 5; p++) acc[r][p] = 0ull;

    auto chan_ptr = [&](int ci) -> const float* {
        if (MODE == 0) return (ci < CH) ? A + (size_t)(b * CH + ci) * HW
                                        : Bp + (size_t)(b * CH + (ci - CH)) * HW;
        else if (MODE == 1) return g_fin + (size_t)(b * 2 * CH + ci) * HW;
        else return g_h + (size_t)(b * CH + ci) * HW;
    };

    auto stage = [&](int ck, int buf) {
        const int ci0 = ck * CC;
        // weights: contiguous [k][co] rows -> cp16 (4 floats each)
        const float* wsrc = wT + (size_t)(ci0 * 9) * WCOLS + co_base;
        for (int idx = tid; idx < NW16; idx += 256) {
            int s = idx / (CO_TILE / 4), j = idx % (CO_TILE / 4);
            cp16(swb + (u32)(buf * SM_WF + s * CO_PAD + j * 4) * 4u,
                 wsrc + (size_t)s * WCOLS + j * 4);
        }
        // inputs (row-pair interleaved float2), zfill halo
        for (int idx = tid; idx < CC * 3 * XW; idx += 256) {
            int ci  = idx / (3 * XW);
            int rem = idx % (3 * XW);
            int ry  = rem / XW;
            int xx  = rem % XW;
            int gx  = xx - 1;
            int gy0 = y0 - 1 + ry;
            int gy1 = gy0 + 1;
            bool okx = (gx >= 0) && (gx < W);
            const float* src = chan_ptr(ci0 + ci) + gy0 * W + gx;
            u32 dst = sib + (u32)(buf * SM_IF + (ci * 3 + ry) * XW + xx) * 8u;
            cp4z(dst,     src,     okx && (gy0 >= 0) && (gy0 < H));
            cp4z(dst + 4, src + W, okx && (gy1 < H));
        }
        cp_commit();
    };

    stage(0, 0);

    for (int ck = 0; ck < NCK; ck++) {
        const int buf = ck & 1;
        if (ck + 1 < NCK) { stage(ck + 1, buf ^ 1); cp_wait1(); }
        else              { cp_wait0(); }
        __syncthreads();

        const float*  wbuf = sW + buf * SM_WF;
        const float2* ibuf = sI + buf * SM_IF;
        for (int ci = 0; ci < CC; ++ci) {
#pragma unroll
            for (int ky = 0; ky < 3; ky++) {
                const ull* ip = reinterpret_cast<const ull*>(&ibuf[(ci * 3 + ky) * XW + x0]);
                ull vv[7];
#pragma unroll
                for (int j = 0; j < 7; j++) vv[j] = ip[j];
#pragma unroll
                for (int kx = 0; kx < 3; kx++) {
                    const int s = ci * KS2 + ky * 3 + kx;
                    const float* wp = &wbuf[s * CO_PAD + tco * RCO];
                    ull w2[RCO];
                    if (RCO == 4) {
                        float4 w4 = *reinterpret_cast<const float4*>(wp);
                        w2[0] = dup2(w4.x); w2[1] = dup2(w4.y);
                        w2[2] = dup2(w4.z); w2[3] = dup2(w4.w);
                    } else {
                        float2 wv = *reinterpret_cast<const float2*>(wp);
                        w2[0] = dup2(wv.x); w2[1] = dup2(wv.y);
                    }
#pragma unroll
                    for (int p = 0; p < 5; p++)
#pragma unroll
                        for (int r = 0; r < RCO; r++) ffma2(acc[r][p], w2[r], vv[kx + p]);
                }
            }
        }
        __syncthreads();
    }

    float* optr = (MODE == 0) ? g_h : (MODE == 3) ? g_off : out_param;
#pragma unroll
    for (int r = 0; r < RCO; r++) {
        int co = co_base + tco * RCO + r;
        if (co >= COUT) continue;
        float bnb, bns = 1.0f, rs = 0.0f;
        if (MODE == 1) {
            float gm = bias_or_bn[co];
            float bt = bias_or_bn[COUT + co];
            float mn = bias_or_bn[2 * COUT + co];
            float vr = bias_or_bn[3 * COUT + co];
            bns = gm * rsqrtf(vr + EPS);
            bnb = bt - mn * bns;
            rs  = *res_scale;
        } else {
            bnb = bias_or_bn[co];
        }
#pragma unroll
        for (int p = 0; p < 5; p++) {
            int x = x0 + p;
            int o0 = ((b * COUT + co) * H + y0) * W + x;
            int o1 = o0 + W;
            float a0, a1;
            unpack2(acc[r][p], a0, a1);
            if (MODE == 0) {
                optr[o0] = silu_(a0 + bnb);
                optr[o1] = silu_(a1 + bnb);
            } else if (MODE == 1) {
                optr[o0] = silu_(a0 * bns + bnb) + rs * g_iral[o0];
                optr[o1] = silu_(a1 * bns + bnb) + rs * g_iral[o1];
            } else {
                optr[o0] = a0 + bnb;
                optr[o1] = a1 + bnb;
            }
        }
    }
}

// ---------------------------------------------------------------------------
// DCN 1x1 conv (Cin=1152 -> 128), cp.async double-buffered, cp16 weights
// ---------------------------------------------------------------------------
constexpr int DCC     = 32;
constexpr int DCO_T   = 64;
constexpr int DCO_PAD = 68;
constexpr int DIELEM  = DCC * W;
constexpr int DSM_W   = DCC * DCO_PAD;
constexpr int DSM_I   = DCC * W;
constexpr int DCN_SMEM = (2 * DSM_W) * 4 + (2 * DSM_I) * 8;

__global__ __launch_bounds__(256)
void dcn_conv_kernel(const float* __restrict__ bias) {
    extern __shared__ float dsm[];
    float*  sW = dsm;
    float2* sI = (float2*)(dsm + 2 * DSM_W);

    const int tid = threadIdx.x;
    const int tco = tid & 15;
    const int tpx = tid >> 4;
    const int x0  = tpx * 5;
    const int b   = blockIdx.x / (H / 2);
    const int y0  = (blockIdx.x % (H / 2)) * 2;
    const int co_base = blockIdx.y * DCO_T;

    const u32 swb = smem_u32(sW);
    const u32 sib = smem_u32(sI);
    const float* vbase = g_vals + (size_t)b * KD * HW + (size_t)y0 * W;

    ull acc[4][5];
#pragma unroll
    for (int r = 0; r < 4; r++)
#pragma unroll
        for (int p = 0; p < 5; p++) acc[r][p] = 0ull;

    auto stage = [&](int ck, int buf) {
        const int ci0 = ck * DCC;
        const float* wsrc = g_wdt + (size_t)ci0 * CH + co_base;
        // 32 s-rows x 16 cp16 = 512 ops, 2 per thread
#pragma unroll
        for (int i = 0; i < (DCC * 16) / 256; i++) {
            int idx = i * 256 + tid;
            int s = idx >> 4, j = idx & 15;
            cp16(swb + (u32)(buf * DSM_W + s * DCO_PAD + j * 4) * 4u,
                 wsrc + (size_t)s * CH + j * 4);
        }
#pragma unroll 2
        for (int i = 0; i < DIELEM / 256; i++) {
            int idx = i * 256 + tid;
            int ci = idx / W, xx = idx % W;
            const float* src = vbase + (size_t)(ci0 + ci) * HW + xx;
            u32 dst = sib + (u32)(buf * DSM_I + ci * W + xx) * 8u;
            cp4(dst, src);
            cp4(dst + 4, src + W);
        }
        cp_commit();
    };

    stage(0, 0);

    constexpr int NCK = KD / DCC;
    for (int ck = 0; ck < NCK; ck++) {
        const int buf = ck & 1;
        if (ck + 1 < NCK) { stage(ck + 1, buf ^ 1); cp_wait1(); }
        else              { cp_wait0(); }
        __syncthreads();

        const float*  wbuf = sW + buf * DSM_W;
        const float2* ibuf = sI + buf * DSM_I;
#pragma unroll 4
        for (int ci = 0; ci < DCC; ++ci) {
            const ull* ip = reinterpret_cast<const ull*>(&ibuf[ci * W + x0]);
            ull vv[5];
#pragma unroll
            for (int p = 0; p < 5; p++) vv[p] = ip[p];
            float4 w4 = *reinterpret_cast<const float4*>(&wbuf[ci * DCO_PAD + tco * 4]);
            ull w2[4] = { dup2(w4.x), dup2(w4.y), dup2(w4.z), dup2(w4.w) };
#pragma unroll
            for (int p = 0; p < 5; p++)
#pragma unroll
                for (int r = 0; r < 4; r++) ffma2(acc[r][p], w2[r], vv[p]);
        }
        __syncthreads();
    }

#pragma unroll
    for (int r = 0; r < 4; r++) {
        int co = co_base + tco * 4 + r;
        float bs = __ldg(&bias[co]);
#pragma unroll
        for (int p = 0; p < 5; p++) {
            int x = x0 + p;
            int o0 = ((b * CH + co) * H + y0) * W + x;
            float a0, a1;
            unpack2(acc[r][p], a0, a1);
            g_iral[o0]     = a0 + bs;
            g_iral[o0 + W] = a1 + bs;
        }
    }
}

// ---------------------------------------------------------------------------
// Deformable bilinear sampling -> g_vals[b][c*9+k][y][x]
// ---------------------------------------------------------------------------
__global__ __launch_bounds__(256)
void deform_kernel(const float* __restrict__ ir) {
    const int blk   = blockIdx.x;
    const int ytile = blk % 27;
    const int bk    = blk / 27;
    const int k     = bk % 9;
    const int b     = bk / 9;
    const int tid   = threadIdx.x;
    if (tid >= 240) return;
    const int y = ytile * 3 + tid / 80;
    const int x = tid % 80;
    if (y >= H) return;

    const float* obase = g_off + (b * 27) * HW + y * W + x;
    float oy = obase[(2 * k) * HW];
    float ox = obase[(2 * k + 1) * HW];
    float m  = sigm_(obase[(18 + k) * HW]);

    const int ky = k / 3 - 1;
    const int kx = k % 3 - 1;
    float ys = oy + (float)(ky + y);
    float xs = ox + (float)(kx + x);
    float fy = floorf(ys), fx = floorf(xs);
    float wy = ys - fy,    wx = xs - fx;
    int y0 = (int)fy, x0 = (int)fx;
    int y1 = y0 + 1,  x1 = x0 + 1;
    bool vy0 = (y0 >= 0) && (y0 < H);
    bool vy1 = (y1 >= 0) && (y1 < H);
    bool vx0 = (x0 >= 0) && (x0 < W);
    bool vx1 = (x1 >= 0) && (x1 < W);
    float w00 = (1.0f - wy) * (1.0f - wx) * m * ((vy0 && vx0) ? 1.0f : 0.0f);
    float w01 = (1.0f - wy) * wx          * m * ((vy0 && vx1) ? 1.0f : 0.0f);
    float w10 = wy          * (1.0f - wx) * m * ((vy1 && vx0) ? 1.0f : 0.0f);
    float w11 = wy          * wx          * m * ((vy1 && vx1) ? 1.0f : 0.0f);
    int cy0 = min(max(y0, 0), H - 1), cy1 = min(max(y1, 0), H - 1);
    int cx0 = min(max(x0, 0), W - 1), cx1 = min(max(x1, 0), W - 1);
    int i00 = cy0 * W + cx0, i01 = cy0 * W + cx1;
    int i10 = cy1 * W + cx0, i11 = cy1 * W + cx1;

    const float* ib = ir + b * CH * HW;
    float* vout = g_vals + ((size_t)b * CH * 9 + k) * HW + y * W + x;
#pragma unroll 4
    for (int c = 0; c < CH; c++) {
        const float* p = ib + c * HW;
        float v = w00 * __ldg(p + i00) + w01 * __ldg(p + i01)
                + w10 * __ldg(p + i10) + w11 * __ldg(p + i11);
        vout[(size_t)c * 9 * HW] = v;
    }
}

// ---------------------------------------------------------------------------
// Gate stage 1: 1x1 conv 256 -> 16 + BN + SiLU -> g_g1
// ---------------------------------------------------------------------------
__global__ __launch_bounds__(256)
void gate1_kernel(const float* __restrict__ rgb,
                  const float* __restrict__ wg1,
                  const float* __restrict__ bng1) {
    __shared__ float sg[2 * CH * MID];
    const int tid = threadIdx.x;
    for (int i = tid; i < 2 * CH * MID; i += 256) {
        int ci = i >> 4, o = i & 15;
        sg[i] = wg1[o * (2 * CH) + ci];
    }
    __syncthreads();
    const int idx = blockIdx.x * 256 + tid;
    if (idx >= Bn * HW) return;
    const int b = idx / HW, p = idx % HW;

    float acc[MID];
#pragma unroll
    for (int o = 0; o < MID; o++) acc[o] = 0.0f;

    const float* rp = rgb    + b * CH * HW + p;
    const float* ip = g_iral + b * CH * HW + p;
    for (int ci = 0; ci < CH; ci++) {
        float v = rp[ci * HW];
        const float* w = &sg[ci * MID];
#pragma unroll
        for (int o = 0; o < MID; o++) acc[o] += w[o] * v;
    }
    for (int ci = 0; ci < CH; ci++) {
        float v = ip[ci * HW];
        const float* w = &sg[(CH + ci) * MID];
#pragma unroll
        for (int o = 0; o < MID; o++) acc[o] += w[o] * v;
    }
#pragma unroll
    for (int o = 0; o < MID; o++) {
        float gm = bng1[o], bt = bng1[MID + o];
        float mn = bng1[2 * MID + o], vr = bng1[3 * MID + o];
        float sc = gm * rsqrtf(vr + EPS);
        g_g1[(b * MID + o) * HW + p] = silu_(acc[o] * sc + bt - mn * sc);
    }
}

// ---------------------------------------------------------------------------
// Gate stages 2+3, then materialize fused conv input g_fin
// ---------------------------------------------------------------------------
__global__ __launch_bounds__(256)
void gate23_kernel(const float* __restrict__ wg2,
                   const float* __restrict__ bng2,
                   const float* __restrict__ wg3,
                   const float* __restrict__ bg3,
                   const float* __restrict__ rgb) {
    const int idx = blockIdx.x * 256 + threadIdx.x;
    if (idx >= Bn * HW) return;
    const int b = idx / HW, p = idx % HW;
    const int y = p / W, x = p % W;

    float s3 = __ldg(bg3);
#pragma unroll
    for (int o = 0; o < MID; o++) {
        const float* gp = g_g1 + (b * MID + o) * HW;
        float s = 0.0f;
#pragma unroll
        for (int ky = 0; ky < 3; ky++) {
            int yy = y + ky - 1;
            if (yy < 0 || yy >= H) continue;
#pragma unroll
            for (int kx = 0; kx < 3; kx++) {
                int xx = x + kx - 1;
                if (xx < 0 || xx >= W) continue;
                s += gp[yy * W + xx] * __ldg(&wg2[o * 9 + ky * 3 + kx]);
            }
        }
        float gm = __ldg(&bng2[o]), bt = __ldg(&bng2[MID + o]);
        float mn = __ldg(&bng2[2 * MID + o]), vr = __ldg(&bng2[3 * MID + o]);
        float sc = gm * rsqrtf(vr + EPS);
        s3 += silu_(s * sc + bt - mn * sc) * __ldg(&wg3[o]);
    }
    float gv = sigm_(s3);
    g_gate[b * HW + p] = gv;

    const float* ip = g_iral + (size_t)b * CH * HW + p;
    const float* rp = rgb    + (size_t)b * CH * HW + p;
    float* f0 = g_fin + (size_t)b * 2 * CH * HW + p;
    float* f1 = f0 + (size_t)CH * HW;
    float om = 1.0f - gv;
#pragma unroll 4
    for (int c = 0; c < CH; c++) {
        f0[(size_t)c * HW] = gv * ip[(size_t)c * HW];
        f1[(size_t)c * HW] = om * rp[(size_t)c * HW];
    }
}

// ---------------------------------------------------------------------------
// Launcher
// ---------------------------------------------------------------------------
extern "C" void kernel_launch(void* const* d_in, const int* in_sizes, int n_in,
                              void* d_out, int out_size) {
    const float* rgb    = (const float*)d_in[0];
    const float* ir     = (const float*)d_in[1];
    const float* w_off1 = (const float*)d_in[2];
    const float* b_off1 = (const float*)d_in[3];
    const float* w_off2 = (const float*)d_in[4];
    const float* b_off2 = (const float*)d_in[5];
    const float* w_dcn  = (const float*)d_in[6];
    const float* b_dcn  = (const float*)d_in[7];
    const float* w_g1   = (const float*)d_in[8];
    const float* bn_g1  = (const float*)d_in[9];
    const float* w_g2   = (const float*)d_in[10];
    const float* bn_g2  = (const float*)d_in[11];
    const float* w_g3   = (const float*)d_in[12];
    const float* b_g3   = (const float*)d_in[13];
    const float* w_f    = (const float*)d_in[14];
    const float* bn_f   = (const float*)d_in[15];
    const float* rscale = (const float*)d_in[16];
    float* out = (float*)d_out;

    float* w0t; cudaGetSymbolAddress((void**)&w0t, g_w0t);
    float* wft; cudaGetSymbolAddress((void**)&wft, g_wft);
    float* wdt; cudaGetSymbolAddress((void**)&wdt, g_wdt);
    float* w2t; cudaGetSymbolAddress((void**)&w2t, g_w2t);

    // double-buffered smem sizes (identical to R6)
    const int sm_big = 2 * ((72 * 68) * 4 + (8 * 3 * 82) * 8);   // 70656 B
    const int sm_off = 2 * ((72 * 36) * 4 + (8 * 3 * 82) * 8);   // 52224 B

    cudaFuncSetAttribute(conv_kernel<0>, cudaFuncAttributeMaxDynamicSharedMemorySize, sm_big);
    cudaFuncSetAttribute(conv_kernel<1>, cudaFuncAttributeMaxDynamicSharedMemorySize, sm_big);
    cudaFuncSetAttribute(conv_kernel<3>, cudaFuncAttributeMaxDynamicSharedMemorySize, sm_off);
    cudaFuncSetAttribute(dcn_conv_kernel, cudaFuncAttributeMaxDynamicSharedMemorySize, DCN_SMEM);

    const int BX = Bn * (H / 2);   // 320 row-pair blocks

    // 0) weight transposes
    prep_w_kernel<<<(2304 * 128 + 255) / 256, 256>>>(w_off1, w0t, 2304, 128, 128);
    prep_w_kernel<<<(2304 * 128 + 255) / 256, 256>>>(w_f,    wft, 2304, 128, 128);
    prep_w_kernel<<<(1152 * 128 + 255) / 256, 256>>>(w_dcn,  wdt, 1152, 128, 128);
    prep_w_kernel<<<(1152 * 32 + 255) / 256, 256>>>(w_off2,  w2t, 1152, 32, 27);

    // 1) h = silu(conv3x3(concat(rgb, ir)))
    conv_kernel<0><<<dim3(BX, 2), 256, sm_big>>>(rgb, ir, w0t, b_off1, nullptr, nullptr);
    // 2) offset/mask conv (27 ch)
    conv_kernel<3><<<dim3(BX, 1), 256, sm_off>>>(nullptr, nullptr, w2t, b_off2, nullptr, nullptr);
    // 3) deformable bilinear sampling * mask -> g_vals
    deform_kernel<<<Bn * 9 * 27, 256>>>(ir);
    // 4) ir_aligned = vals . w_dcn + b_dcn
    dcn_conv_kernel<<<dim3(BX, 2), 256, DCN_SMEM>>>(b_dcn);
    // 5) gate stage 1
    gate1_kernel<<<(Bn * HW + 255) / 256, 256>>>(rgb, w_g1, bn_g1);
    // 6) gate stages 2+3 + fused-input materialization
    gate23_kernel<<<(Bn * HW + 255) / 256, 256>>>(w_g2, bn_g2, w_g3, b_g3, rgb);
    // 7) fused conv + BN + SiLU + residual -> out
    conv_kernel<1><<<dim3(BX, 2), 256, sm_big>>>(nullptr, nullptr, wft, bn_f, rscale, out);
}